// round 4
// baseline (speedup 1.0000x reference)
#include <cuda_runtime.h>
#include <cstdint>

// Problem constants (shapes fixed by the reference)
#define IN_DIM   128          // z feature dim
#define KDIM     256          // 2*IN_DIM
#define HID      64           // hidden
#define TILE_E   128          // edges per block tile
#define AS_LD    260          // As row stride in words (256 + 4 pad -> conflict-free frags)
#define W1_LD    72           // W1s row stride in words (64 + 8 pad -> conflict-free frags)

#define SMEM_WORDS (KDIM*W1_LD + TILE_E*AS_LD + 64 + 64 + 1)
#define SMEM_BYTES (SMEM_WORDS * 4)

__device__ __forceinline__ uint32_t f2tf32(float x) {
    uint32_t r;
    asm("cvt.rna.tf32.f32 %0, %1;" : "=r"(r) : "f"(x));
    return r;
}

__device__ __forceinline__ void mma_tf32(float* c,
                                         uint32_t a0, uint32_t a1, uint32_t a2, uint32_t a3,
                                         uint32_t b0, uint32_t b1) {
    asm volatile(
        "mma.sync.aligned.m16n8k8.row.col.f32.tf32.tf32.f32 "
        "{%0,%1,%2,%3}, {%4,%5,%6,%7}, {%8,%9}, {%0,%1,%2,%3};"
        : "+f"(c[0]), "+f"(c[1]), "+f"(c[2]), "+f"(c[3])
        : "r"(a0), "r"(a1), "r"(a2), "r"(a3), "r"(b0), "r"(b1));
}

__global__ __launch_bounds__(256, 1)
void mask_predictor_kernel(const float* __restrict__ z,
                           const void* __restrict__ eidx_raw,
                           const float* __restrict__ W1,
                           const float* __restrict__ b1,
                           const float* __restrict__ W2,
                           const float* __restrict__ b2,
                           float* __restrict__ out,
                           int NE) {
    extern __shared__ unsigned char smem_raw[];
    uint32_t* W1s = reinterpret_cast<uint32_t*>(smem_raw);       // [256][72] tf32
    uint32_t* As  = W1s + KDIM * W1_LD;                          // [128][260] tf32
    float*    b1s = reinterpret_cast<float*>(As + TILE_E * AS_LD);
    float*    w2s = b1s + 64;
    float*    b2s = w2s + 64;

    const int tid  = threadIdx.x;
    const int warp = tid >> 5;
    const int lane = tid & 31;
    const int g    = lane >> 2;   // groupID
    const int m    = lane & 3;    // threadID_in_group

    // ---- Detect edge_index dtype (int32 vs int64) uniformly ----
    // If int64: indices < 100000 -> all high 32-bit words are zero.
    // If int32: odd words are independent random indices (never all zero).
    const int*       e32 = reinterpret_cast<const int*>(eidx_raw);
    const long long* e64 = reinterpret_cast<const long long*>(eidx_raw);
    bool is64 = true;
    #pragma unroll
    for (int i = 1; i < 32; i += 2) {
        if (e32[i] != 0) is64 = false;
    }

    // ---- Stage W1 (tf32), b1, W2, b2 once per block ----
    for (int i = tid; i < KDIM * HID; i += 256) {
        W1s[(i >> 6) * W1_LD + (i & 63)] = f2tf32(W1[i]);
    }
    if (tid < 64) { b1s[tid] = b1[tid]; w2s[tid] = W2[tid]; }
    if (tid == 0) { b2s[0] = b2[0]; }
    __syncthreads();

    const int nTiles = (NE + TILE_E - 1) / TILE_E;

    for (int tile = blockIdx.x; tile < nTiles; tile += gridDim.x) {
        const int tileBase = tile * TILE_E;

        // ---- Gather: 16 edges per warp, each row = z[src] (128f) | z[dst] (128f) ----
        #pragma unroll 4
        for (int i = 0; i < 16; i++) {
            const int e  = warp * 16 + i;
            const int ge = tileBase + e;

            long long s = 0, d = 0;
            if (ge < NE) {
                if (is64) {
                    s = e64[ge];
                    d = e64[(long long)NE + ge];
                } else {
                    s = (long long)e32[ge];
                    d = (long long)e32[NE + ge];
                }
            }

            float4 v = reinterpret_cast<const float4*>(z)[s * (IN_DIM / 4) + lane];
            uint4 t4;
            t4.x = f2tf32(v.x); t4.y = f2tf32(v.y); t4.z = f2tf32(v.z); t4.w = f2tf32(v.w);
            reinterpret_cast<uint4*>(&As[e * AS_LD])[lane] = t4;

            v = reinterpret_cast<const float4*>(z)[d * (IN_DIM / 4) + lane];
            t4.x = f2tf32(v.x); t4.y = f2tf32(v.y); t4.z = f2tf32(v.z); t4.w = f2tf32(v.w);
            reinterpret_cast<uint4*>(&As[e * AS_LD + IN_DIM])[lane] = t4;
        }
        __syncthreads();

        // ---- GEMM: warp computes 16 edges x 64 cols via m16n8k8 tf32 ----
        float acc[8][4];
        #pragma unroll
        for (int nt = 0; nt < 8; nt++)
            #pragma unroll
            for (int r = 0; r < 4; r++) acc[nt][r] = 0.f;

        const int arow0 = (warp * 16 + g) * AS_LD;

        #pragma unroll 4
        for (int kt = 0; kt < 32; kt++) {
            const int k0 = kt * 8;
            const uint32_t a0 = As[arow0 + k0 + m];
            const uint32_t a1 = As[arow0 + 8 * AS_LD + k0 + m];
            const uint32_t a2 = As[arow0 + k0 + m + 4];
            const uint32_t a3 = As[arow0 + 8 * AS_LD + k0 + m + 4];
            const uint32_t* w1k0 = &W1s[(k0 + m) * W1_LD];
            const uint32_t* w1k4 = &W1s[(k0 + m + 4) * W1_LD];
            #pragma unroll
            for (int nt = 0; nt < 8; nt++) {
                const uint32_t b0 = w1k0[nt * 8 + g];
                const uint32_t b1v = w1k4[nt * 8 + g];
                mma_tf32(acc[nt], a0, a1, a2, a3, b0, b1v);
            }
        }

        // ---- Epilogue: bias + ReLU + W2 dot + sigmoid ----
        // Lane holds cols {nt*8 + 2m, nt*8 + 2m + 1} for rows g and g+8.
        float p0 = 0.f, p1 = 0.f;
        #pragma unroll
        for (int nt = 0; nt < 8; nt++) {
            const int c = nt * 8 + 2 * m;
            const float ba = b1s[c], bb = b1s[c + 1];
            const float wa = w2s[c], wb = w2s[c + 1];
            float h;
            h = acc[nt][0] + ba; p0 += fmaxf(h, 0.f) * wa;
            h = acc[nt][1] + bb; p0 += fmaxf(h, 0.f) * wb;
            h = acc[nt][2] + ba; p1 += fmaxf(h, 0.f) * wa;
            h = acc[nt][3] + bb; p1 += fmaxf(h, 0.f) * wb;
        }
        p0 += __shfl_xor_sync(0xffffffffu, p0, 1);
        p0 += __shfl_xor_sync(0xffffffffu, p0, 2);
        p1 += __shfl_xor_sync(0xffffffffu, p1, 1);
        p1 += __shfl_xor_sync(0xffffffffu, p1, 2);

        if (m == 0) {
            const float bias2 = b2s[0];
            const int e0 = tileBase + warp * 16 + g;
            if (e0 < NE)
                out[e0] = 1.f / (1.f + __expf(-(p0 + bias2)));
            if (e0 + 8 < NE)
                out[e0 + 8] = 1.f / (1.f + __expf(-(p1 + bias2)));
        }
        __syncthreads();  // protect As before next tile's gather
    }
}

extern "C" void kernel_launch(void* const* d_in, const int* in_sizes, int n_in,
                              void* d_out, int out_size) {
    const float* z    = (const float*)d_in[0];
    const void*  eidx = d_in[1];
    const float* W1   = (const float*)d_in[2];
    const float* b1   = (const float*)d_in[3];
    const float* W2   = (const float*)d_in[4];
    const float* b2   = (const float*)d_in[5];
    float*       out  = (float*)d_out;

    const int NE = in_sizes[1] / 2;  // edge_index is (2, E)

    static bool attr_set = false;
    if (!attr_set) {
        cudaFuncSetAttribute(mask_predictor_kernel,
                             cudaFuncAttributeMaxDynamicSharedMemorySize, SMEM_BYTES);
        attr_set = true;
    }

    mask_predictor_kernel<<<152, 256, SMEM_BYTES>>>(z, eidx, W1, b1, W2, b2, out, NE);
}

// round 5
// speedup vs baseline: 3.0658x; 3.0658x over previous
#include <cuda_runtime.h>
#include <cuda_fp16.h>
#include <cstdint>

// Shapes fixed by the reference
#define N_NODES  100000
#define IN_DIM   128
#define KDIM     256          // 2*IN_DIM
#define HID      64
#define TILE_E   256          // edges per block tile (8 warps x 32 edges)
#define LDAS     132          // As row stride in 32-bit words (128 data + 4 pad)
#define LDW      132          // W1t row stride in 32-bit words (128 data + 4 pad)

#define SMEM_BYTES (TILE_E*LDAS*4 + HID*LDW*4 + (64+64+1)*4)

// fp16 copy of z, gathered via cp.async (25.6 MB static scratch)
__device__ __half zh_g[N_NODES * IN_DIM];

__global__ void convert_z_kernel(const float* __restrict__ z, int n) {
    const int stride = gridDim.x * blockDim.x;
    const int n4 = n >> 2;
    const float4* z4 = reinterpret_cast<const float4*>(z);
    __half2* o2 = reinterpret_cast<__half2*>(zh_g);
    for (int i = blockIdx.x * blockDim.x + threadIdx.x; i < n4; i += stride) {
        float4 v = z4[i];
        o2[i * 2 + 0] = __floats2half2_rn(v.x, v.y);
        o2[i * 2 + 1] = __floats2half2_rn(v.z, v.w);
    }
}

__device__ __forceinline__ void mma_fp16(float* c, const uint32_t* a,
                                         uint32_t b0, uint32_t b1) {
    asm volatile(
        "mma.sync.aligned.m16n8k16.row.col.f32.f16.f16.f32 "
        "{%0,%1,%2,%3}, {%4,%5,%6,%7}, {%8,%9}, {%0,%1,%2,%3};"
        : "+f"(c[0]), "+f"(c[1]), "+f"(c[2]), "+f"(c[3])
        : "r"(a[0]), "r"(a[1]), "r"(a[2]), "r"(a[3]), "r"(b0), "r"(b1));
}

__global__ __launch_bounds__(256, 1)
void mask_predictor_kernel(const void* __restrict__ eidx_raw,
                           const float* __restrict__ W1,
                           const float* __restrict__ b1,
                           const float* __restrict__ W2,
                           const float* __restrict__ b2,
                           float* __restrict__ out,
                           int NE) {
    extern __shared__ unsigned char smem_raw[];
    uint32_t* As32  = reinterpret_cast<uint32_t*>(smem_raw);     // [256][132] words (fp16x2)
    uint32_t* W1t32 = As32 + TILE_E * LDAS;                      // [64][132] words (W1^T, fp16x2)
    float*    b1s   = reinterpret_cast<float*>(W1t32 + HID * LDW);
    float*    w2s   = b1s + 64;
    float*    b2s   = w2s + 64;
    __half*   W1th  = reinterpret_cast<__half*>(W1t32);          // halves, row stride 264

    const int tid  = threadIdx.x;
    const int warp = tid >> 5;
    const int lane = tid & 31;
    const int g    = lane >> 2;   // groupID (0..7)
    const int m    = lane & 3;    // thread-in-group (0..3)

    // ---- Detect edge_index dtype (int64 vs int32) uniformly ----
    // int64 indices < 100000 => all high words zero; int32 => odd words random.
    const int*       e32 = reinterpret_cast<const int*>(eidx_raw);
    const long long* e64 = reinterpret_cast<const long long*>(eidx_raw);
    bool is64 = true;
    #pragma unroll
    for (int i = 1; i < 32; i += 2) if (e32[i] != 0) is64 = false;

    // ---- Stage W1^T (fp16), b1, W2, b2 ----
    for (int i = tid; i < KDIM * HID; i += 256) {
        const int k = i >> 6, n = i & 63;
        W1th[n * (LDW * 2) + k] = __float2half(W1[i]);
    }
    if (tid < 64) { b1s[tid] = b1[tid]; w2s[tid] = W2[tid]; }
    if (tid == 0) { b2s[0] = b2[0]; }
    __syncthreads();

    const char* zb = reinterpret_cast<const char*>(zh_g);
    const int nTiles = (NE + TILE_E - 1) / TILE_E;
    const int warpE  = warp * 32;           // local row base (32 edges per warp)
    const int halfSel = lane >> 4;          // 0: src half-row, 1: dst half-row
    const int sub     = lane & 15;          // 16B chunk within 256B half-row

    for (int tile = blockIdx.x; tile < nTiles; tile += gridDim.x) {
        const int tileBase = tile * TILE_E;

        // ---- Gather: lane owns edge (warpE+lane); broadcast indices via shfl;
        //      32 lanes move 512 B/edge (src|dst fp16 rows) via cp.async.cg ----
        const int ge = tileBase + warpE + lane;
        long long sIdx = 0, dIdx = 0;
        if (ge < NE) {
            if (is64) { sIdx = e64[ge]; dIdx = e64[(long long)NE + ge]; }
            else      { sIdx = (long long)e32[ge]; dIdx = (long long)e32[NE + ge]; }
        }
        #pragma unroll 8
        for (int i = 0; i < 32; i++) {
            const long long s = __shfl_sync(0xffffffffu, sIdx, i);
            const long long d = __shfl_sync(0xffffffffu, dIdx, i);
            const long long row = halfSel ? d : s;
            const char* src = zb + (row << 8) + sub * 16;
            char* dstp = reinterpret_cast<char*>(As32)
                       + (warpE + i) * (LDAS * 4) + halfSel * 256 + sub * 16;
            const uint32_t daddr = (uint32_t)__cvta_generic_to_shared(dstp);
            asm volatile("cp.async.cg.shared.global [%0], [%1], 16;\n"
                         :: "r"(daddr), "l"(src));
        }
        asm volatile("cp.async.commit_group;\n");
        asm volatile("cp.async.wait_group 0;\n" ::: "memory");
        __syncthreads();

        // ---- GEMM: warp computes 32 edges x 64 cols, fp16 m16n8k16, fp32 acc ----
        float acc[2][8][4];
        #pragma unroll
        for (int mt = 0; mt < 2; mt++)
            #pragma unroll
            for (int nt = 0; nt < 8; nt++)
                #pragma unroll
                for (int r = 0; r < 4; r++) acc[mt][nt][r] = 0.f;

        #pragma unroll 4
        for (int kt = 0; kt < 16; kt++) {
            const int kw = kt * 8 + m;
            uint32_t a[2][4];
            #pragma unroll
            for (int mt = 0; mt < 2; mt++) {
                const int base = (warpE + mt * 16 + g) * LDAS;
                a[mt][0] = As32[base + kw];
                a[mt][1] = As32[base + 8 * LDAS + kw];
                a[mt][2] = As32[base + kw + 4];
                a[mt][3] = As32[base + 8 * LDAS + kw + 4];
            }
            #pragma unroll
            for (int nt = 0; nt < 8; nt++) {
                const uint32_t b0  = W1t32[(nt * 8 + g) * LDW + kw];
                const uint32_t b1v = W1t32[(nt * 8 + g) * LDW + kw + 4];
                mma_fp16(acc[0][nt], a[0], b0, b1v);
                mma_fp16(acc[1][nt], a[1], b0, b1v);
            }
        }

        // ---- Epilogue: bias + ReLU + W2 dot + sigmoid ----
        // Lane holds cols {nt*8+2m, +1} for rows (warpE + mt*16 + g) and (+8).
        float p[4] = {0.f, 0.f, 0.f, 0.f};  // rows g, g+8, g+16, g+24
        #pragma unroll
        for (int mt = 0; mt < 2; mt++) {
            #pragma unroll
            for (int nt = 0; nt < 8; nt++) {
                const int c = nt * 8 + 2 * m;
                const float ba = b1s[c], bb = b1s[c + 1];
                const float wa = w2s[c], wb = w2s[c + 1];
                float h;
                h = acc[mt][nt][0] + ba; p[mt * 2 + 0] += fmaxf(h, 0.f) * wa;
                h = acc[mt][nt][1] + bb; p[mt * 2 + 0] += fmaxf(h, 0.f) * wb;
                h = acc[mt][nt][2] + ba; p[mt * 2 + 1] += fmaxf(h, 0.f) * wa;
                h = acc[mt][nt][3] + bb; p[mt * 2 + 1] += fmaxf(h, 0.f) * wb;
            }
        }
        #pragma unroll
        for (int j = 0; j < 4; j++) {
            p[j] += __shfl_xor_sync(0xffffffffu, p[j], 1);
            p[j] += __shfl_xor_sync(0xffffffffu, p[j], 2);
        }
        if (m == 0) {
            const float bias2 = b2s[0];
            #pragma unroll
            for (int j = 0; j < 4; j++) {
                const int e = tileBase + warpE + (j >> 1) * 16 + (j & 1) * 8 + g;
                if (e < NE)
                    out[e] = 1.f / (1.f + __expf(-(p[j] + bias2)));
            }
        }
        __syncthreads();  // all warps done reading As before next tile's gather
    }
}

extern "C" void kernel_launch(void* const* d_in, const int* in_sizes, int n_in,
                              void* d_out, int out_size) {
    const float* z    = (const float*)d_in[0];
    const void*  eidx = d_in[1];
    const float* W1   = (const float*)d_in[2];
    const float* b1   = (const float*)d_in[3];
    const float* W2   = (const float*)d_in[4];
    const float* b2   = (const float*)d_in[5];
    float*       out  = (float*)d_out;

    const int NE = in_sizes[1] / 2;  // edge_index is (2, E)
    const int nZ = in_sizes[0];      // N_NODES * IN_DIM

    static bool attr_set = false;
    if (!attr_set) {
        cudaFuncSetAttribute(mask_predictor_kernel,
                             cudaFuncAttributeMaxDynamicSharedMemorySize, SMEM_BYTES);
        attr_set = true;
    }

    convert_z_kernel<<<152, 256>>>(z, nZ);
    mask_predictor_kernel<<<152, 256, SMEM_BYTES>>>(eidx, W1, b1, W2, b2, out, NE);
}

// round 6
// speedup vs baseline: 3.6530x; 1.1915x over previous
#include <cuda_runtime.h>
#include <cuda_fp16.h>
#include <cstdint>

// Shapes fixed by the reference
#define N_NODES  100000
#define IN_DIM   128
#define KDIM     256          // 2*IN_DIM
#define HID      64
#define NTHREADS 128          // 4 warps per block
#define TILE_E   128          // edges per block tile (4 warps x 32 edges)
#define LDAS     132          // As row stride in 32-bit words (128 data + 4 pad)
#define LDW      132          // W1t row stride in 32-bit words (128 data + 4 pad)
#define GRID     304          // 2 blocks per SM

#define SMEM_BYTES (TILE_E*LDAS*4 + HID*LDW*4 + (64+64+1)*4)

// fp16 copy of z, gathered via cp.async (25.6 MB static scratch)
__device__ __half zh_g[N_NODES * IN_DIM];

__global__ void convert_z_kernel(const float* __restrict__ z, int n) {
    const int stride = gridDim.x * blockDim.x;
    const int n4 = n >> 2;
    const float4* z4 = reinterpret_cast<const float4*>(z);
    __half2* o2 = reinterpret_cast<__half2*>(zh_g);
    for (int i = blockIdx.x * blockDim.x + threadIdx.x; i < n4; i += stride) {
        float4 v = z4[i];
        o2[i * 2 + 0] = __floats2half2_rn(v.x, v.y);
        o2[i * 2 + 1] = __floats2half2_rn(v.z, v.w);
    }
}

__device__ __forceinline__ void mma_fp16(float* c, const uint32_t* a,
                                         uint32_t b0, uint32_t b1) {
    asm volatile(
        "mma.sync.aligned.m16n8k16.row.col.f32.f16.f16.f32 "
        "{%0,%1,%2,%3}, {%4,%5,%6,%7}, {%8,%9}, {%0,%1,%2,%3};"
        : "+f"(c[0]), "+f"(c[1]), "+f"(c[2]), "+f"(c[3])
        : "r"(a[0]), "r"(a[1]), "r"(a[2]), "r"(a[3]), "r"(b0), "r"(b1));
}

struct GatherCtx {
    const int* e32;
    const long long* e64;
    bool is64;
    const char* zb;
    uint32_t* As32;
    int NE, warpE, lane, halfSel, sub;
};

// Issue cp.async gather for one tile (no waits inside).
__device__ __forceinline__ void issue_gather(const GatherCtx& c, int tile) {
    const int ge = tile * TILE_E + c.warpE + c.lane;
    long long sIdx = 0, dIdx = 0;
    if (ge < c.NE) {
        if (c.is64) { sIdx = c.e64[ge]; dIdx = c.e64[(long long)c.NE + ge]; }
        else        { sIdx = (long long)c.e32[ge]; dIdx = (long long)c.e32[c.NE + ge]; }
    }
    #pragma unroll 8
    for (int i = 0; i < 32; i++) {
        const long long s = __shfl_sync(0xffffffffu, sIdx, i);
        const long long d = __shfl_sync(0xffffffffu, dIdx, i);
        const long long row = c.halfSel ? d : s;
        const char* src = c.zb + (row << 8) + c.sub * 16;
        char* dstp = reinterpret_cast<char*>(c.As32)
                   + (c.warpE + i) * (LDAS * 4) + c.halfSel * 256 + c.sub * 16;
        const uint32_t daddr = (uint32_t)__cvta_generic_to_shared(dstp);
        asm volatile("cp.async.cg.shared.global [%0], [%1], 16;\n"
                     :: "r"(daddr), "l"(src));
    }
    asm volatile("cp.async.commit_group;\n");
}

__global__ __launch_bounds__(NTHREADS, 2)
void mask_predictor_kernel(const void* __restrict__ eidx_raw,
                           const float* __restrict__ W1,
                           const float* __restrict__ b1,
                           const float* __restrict__ W2,
                           const float* __restrict__ b2,
                           float* __restrict__ out,
                           int NE) {
    extern __shared__ unsigned char smem_raw[];
    uint32_t* As32  = reinterpret_cast<uint32_t*>(smem_raw);     // [128][132] words (fp16x2)
    uint32_t* W1t32 = As32 + TILE_E * LDAS;                      // [64][132] words (W1^T, fp16x2)
    float*    b1s   = reinterpret_cast<float*>(W1t32 + HID * LDW);
    float*    w2s   = b1s + 64;
    float*    b2s   = w2s + 64;
    __half*   W1th  = reinterpret_cast<__half*>(W1t32);          // halves, row stride 264

    const int tid  = threadIdx.x;
    const int warp = tid >> 5;
    const int lane = tid & 31;
    const int g    = lane >> 2;   // groupID (0..7)
    const int m    = lane & 3;    // thread-in-group (0..3)

    // ---- Detect edge_index dtype (int64 vs int32) uniformly ----
    const int*       e32 = reinterpret_cast<const int*>(eidx_raw);
    const long long* e64 = reinterpret_cast<const long long*>(eidx_raw);
    bool is64 = true;
    #pragma unroll
    for (int i = 1; i < 32; i += 2) if (e32[i] != 0) is64 = false;

    // ---- Stage W1^T (fp16), b1, W2, b2 ----
    for (int i = tid; i < KDIM * HID; i += NTHREADS) {
        const int k = i >> 6, n = i & 63;
        W1th[n * (LDW * 2) + k] = __float2half(W1[i]);
    }
    if (tid < 64) { b1s[tid] = b1[tid]; w2s[tid] = W2[tid]; }
    if (tid == 64) { b2s[0] = b2[0]; }
    __syncthreads();

    GatherCtx ctx;
    ctx.e32 = e32; ctx.e64 = e64; ctx.is64 = is64;
    ctx.zb = reinterpret_cast<const char*>(zh_g);
    ctx.As32 = As32; ctx.NE = NE;
    ctx.warpE = warp * 32;
    ctx.lane = lane;
    ctx.halfSel = lane >> 4;
    ctx.sub = lane & 15;

    const int nTiles = (NE + TILE_E - 1) / TILE_E;
    const int warpE  = ctx.warpE;

    int tile = blockIdx.x;
    if (tile < nTiles) issue_gather(ctx, tile);

    for (; tile < nTiles; tile += gridDim.x) {
        asm volatile("cp.async.wait_group 0;\n" ::: "memory");
        __syncthreads();

        // ---- GEMM: warp computes 32 edges x 64 cols, fp16 m16n8k16, fp32 acc ----
        float acc[2][8][4];
        #pragma unroll
        for (int mt = 0; mt < 2; mt++)
            #pragma unroll
            for (int nt = 0; nt < 8; nt++)
                #pragma unroll
                for (int r = 0; r < 4; r++) acc[mt][nt][r] = 0.f;

        #pragma unroll 4
        for (int kt = 0; kt < 16; kt++) {
            const int kw = kt * 8 + m;
            uint32_t a[2][4];
            #pragma unroll
            for (int mt = 0; mt < 2; mt++) {
                const int base = (warpE + mt * 16 + g) * LDAS;
                a[mt][0] = As32[base + kw];
                a[mt][1] = As32[base + 8 * LDAS + kw];
                a[mt][2] = As32[base + kw + 4];
                a[mt][3] = As32[base + 8 * LDAS + kw + 4];
            }
            #pragma unroll
            for (int nt = 0; nt < 8; nt++) {
                const uint32_t b0  = W1t32[(nt * 8 + g) * LDW + kw];
                const uint32_t b1v = W1t32[(nt * 8 + g) * LDW + kw + 4];
                mma_fp16(acc[0][nt], a[0], b0, b1v);
                mma_fp16(acc[1][nt], a[1], b0, b1v);
            }
        }

        __syncthreads();  // all warps done reading As

        // ---- Prefetch next tile's gather; overlaps epilogue + peer block ----
        const int nxt = tile + gridDim.x;
        if (nxt < nTiles) issue_gather(ctx, nxt);

        // ---- Epilogue: bias + ReLU + W2 dot + sigmoid ----
        float p[4] = {0.f, 0.f, 0.f, 0.f};  // rows g, g+8, g+16, g+24
        #pragma unroll
        for (int mt = 0; mt < 2; mt++) {
            #pragma unroll
            for (int nt = 0; nt < 8; nt++) {
                const int c = nt * 8 + 2 * m;
                const float ba = b1s[c], bb = b1s[c + 1];
                const float wa = w2s[c], wb = w2s[c + 1];
                float h;
                h = acc[mt][nt][0] + ba; p[mt * 2 + 0] += fmaxf(h, 0.f) * wa;
                h = acc[mt][nt][1] + bb; p[mt * 2 + 0] += fmaxf(h, 0.f) * wb;
                h = acc[mt][nt][2] + ba; p[mt * 2 + 1] += fmaxf(h, 0.f) * wa;
                h = acc[mt][nt][3] + bb; p[mt * 2 + 1] += fmaxf(h, 0.f) * wb;
            }
        }
        #pragma unroll
        for (int j = 0; j < 4; j++) {
            p[j] += __shfl_xor_sync(0xffffffffu, p[j], 1);
            p[j] += __shfl_xor_sync(0xffffffffu, p[j], 2);
        }
        if (m == 0) {
            const float bias2 = b2s[0];
            const int tileBase = tile * TILE_E;
            #pragma unroll
            for (int j = 0; j < 4; j++) {
                const int e = tileBase + warpE + (j >> 1) * 16 + (j & 1) * 8 + g;
                if (e < NE)
                    out[e] = 1.f / (1.f + __expf(-(p[j] + bias2)));
            }
        }
    }
}

extern "C" void kernel_launch(void* const* d_in, const int* in_sizes, int n_in,
                              void* d_out, int out_size) {
    const float* z    = (const float*)d_in[0];
    const void*  eidx = d_in[1];
    const float* W1   = (const float*)d_in[2];
    const float* b1   = (const float*)d_in[3];
    const float* W2   = (const float*)d_in[4];
    const float* b2   = (const float*)d_in[5];
    float*       out  = (float*)d_out;

    const int NE = in_sizes[1] / 2;  // edge_index is (2, E)
    const int nZ = in_sizes[0];      // N_NODES * IN_DIM

    static bool attr_set = false;
    if (!attr_set) {
        cudaFuncSetAttribute(mask_predictor_kernel,
                             cudaFuncAttributeMaxDynamicSharedMemorySize, SMEM_BYTES);
        attr_set = true;
    }

    convert_z_kernel<<<152, 256>>>(z, nZ);
    mask_predictor_kernel<<<GRID, NTHREADS, SMEM_BYTES>>>(eidx, W1, b1, W2, b2, out, NE);
}

// round 7
// speedup vs baseline: 3.9995x; 1.0949x over previous
#include <cuda_runtime.h>
#include <cuda_fp16.h>
#include <cstdint>

// Shapes fixed by the reference
#define N_NODES  100000
#define IN_DIM   128
#define KDIM     256          // 2*IN_DIM
#define HID      64
#define NTHREADS 128          // 4 warps per block
#define TILE_E   128          // edges per block tile (4 warps x 32 edges)
#define LDAS     132          // As row stride in 32-bit words (128 data + 4 pad)
#define LDW      132          // W1t row stride in 32-bit words (128 data + 4 pad)
#define GRID     304          // 2 blocks per SM

#define SMEM_BYTES (TILE_E*LDAS*4 + HID*LDW*4 + (64+64+1)*4)

// fp16 copy of z, gathered via cp.async (25.6 MB static scratch)
__device__ __half zh_g[N_NODES * IN_DIM];

__global__ void convert_z_kernel(const float* __restrict__ z, int n) {
    const int stride = gridDim.x * blockDim.x;
    const int n4 = n >> 2;
    const float4* z4 = reinterpret_cast<const float4*>(z);
    __half2* o2 = reinterpret_cast<__half2*>(zh_g);
    for (int i = blockIdx.x * blockDim.x + threadIdx.x; i < n4; i += stride) {
        float4 v = z4[i];
        o2[i * 2 + 0] = __floats2half2_rn(v.x, v.y);
        o2[i * 2 + 1] = __floats2half2_rn(v.z, v.w);
    }
}

__device__ __forceinline__ void mma_fp16(float* c, const uint32_t* a,
                                         uint32_t b0, uint32_t b1) {
    asm volatile(
        "mma.sync.aligned.m16n8k16.row.col.f32.f16.f16.f32 "
        "{%0,%1,%2,%3}, {%4,%5,%6,%7}, {%8,%9}, {%0,%1,%2,%3};"
        : "+f"(c[0]), "+f"(c[1]), "+f"(c[2]), "+f"(c[3])
        : "r"(a[0]), "r"(a[1]), "r"(a[2]), "r"(a[3]), "r"(b0), "r"(b1));
}

struct GatherCtx {
    const int* e32;
    const long long* e64;
    bool is64;
    const char* zb;
    uint32_t* As32;
    int NE, warpE, lane, halfSel, sub;
};

// Issue cp.async gather for one tile's 32 warp-owned rows (no waits inside).
// All addresses are warp-private: rows warpE..warpE+31 only.
__device__ __forceinline__ void issue_gather(const GatherCtx& c, int tile) {
    const int ge = tile * TILE_E + c.warpE + c.lane;
    long long sIdx = 0, dIdx = 0;
    if (ge < c.NE) {
        if (c.is64) { sIdx = c.e64[ge]; dIdx = c.e64[(long long)c.NE + ge]; }
        else        { sIdx = (long long)c.e32[ge]; dIdx = (long long)c.e32[c.NE + ge]; }
    }
    #pragma unroll 8
    for (int i = 0; i < 32; i++) {
        const long long s = __shfl_sync(0xffffffffu, sIdx, i);
        const long long d = __shfl_sync(0xffffffffu, dIdx, i);
        const long long row = c.halfSel ? d : s;
        const char* src = c.zb + (row << 8) + c.sub * 16;
        char* dstp = reinterpret_cast<char*>(c.As32)
                   + (c.warpE + i) * (LDAS * 4) + c.halfSel * 256 + c.sub * 16;
        const uint32_t daddr = (uint32_t)__cvta_generic_to_shared(dstp);
        asm volatile("cp.async.cg.shared.global [%0], [%1], 16;\n"
                     :: "r"(daddr), "l"(src));
    }
    asm volatile("cp.async.commit_group;\n");
}

__global__ __launch_bounds__(NTHREADS, 2)
void mask_predictor_kernel(const void* __restrict__ eidx_raw,
                           const float* __restrict__ W1,
                           const float* __restrict__ b1,
                           const float* __restrict__ W2,
                           const float* __restrict__ b2,
                           float* __restrict__ out,
                           int NE) {
    extern __shared__ unsigned char smem_raw[];
    uint32_t* As32  = reinterpret_cast<uint32_t*>(smem_raw);     // [128][132] words (fp16x2)
    uint32_t* W1t32 = As32 + TILE_E * LDAS;                      // [64][132] words (W1^T, fp16x2)
    float*    b1s   = reinterpret_cast<float*>(W1t32 + HID * LDW);
    float*    w2s   = b1s + 64;
    float*    b2s   = w2s + 64;
    __half*   W1th  = reinterpret_cast<__half*>(W1t32);          // halves, row stride 264

    const int tid  = threadIdx.x;
    const int warp = tid >> 5;
    const int lane = tid & 31;
    const int g    = lane >> 2;   // groupID (0..7)
    const int m    = lane & 3;    // thread-in-group (0..3)

    // ---- Detect edge_index dtype (int64 vs int32) uniformly ----
    const int*       e32 = reinterpret_cast<const int*>(eidx_raw);
    const long long* e64 = reinterpret_cast<const long long*>(eidx_raw);
    bool is64 = true;
    #pragma unroll
    for (int i = 1; i < 32; i += 2) if (e32[i] != 0) is64 = false;

    // ---- Stage W1^T (fp16), b1, W2, b2 (read-only after this barrier) ----
    for (int i = tid; i < KDIM * HID; i += NTHREADS) {
        const int k = i >> 6, n = i & 63;
        W1th[n * (LDW * 2) + k] = __float2half(W1[i]);
    }
    if (tid < 64) { b1s[tid] = b1[tid]; w2s[tid] = W2[tid]; }
    if (tid == 64) { b2s[0] = b2[0]; }
    __syncthreads();

    GatherCtx ctx;
    ctx.e32 = e32; ctx.e64 = e64; ctx.is64 = is64;
    ctx.zb = reinterpret_cast<const char*>(zh_g);
    ctx.As32 = As32; ctx.NE = NE;
    ctx.warpE = warp * 32;
    ctx.lane = lane;
    ctx.halfSel = lane >> 4;
    ctx.sub = lane & 15;

    const int nTiles = (NE + TILE_E - 1) / TILE_E;
    const int warpE  = ctx.warpE;

    // Each warp is a fully independent pipeline over its own 32 As rows:
    // no block barriers in the loop — stalled warps are hidden by the other
    // 7 warps on the SM (2 blocks x 4 warps).
    int tile = blockIdx.x;
    if (tile < nTiles) issue_gather(ctx, tile);

    for (; tile < nTiles; tile += gridDim.x) {
        asm volatile("cp.async.wait_group 0;\n" ::: "memory");
        __syncwarp();   // make lane-written As rows visible warp-wide

        // ---- GEMM: warp computes 32 edges x 64 cols, fp16 m16n8k16, fp32 acc ----
        float acc[2][8][4];
        #pragma unroll
        for (int mt = 0; mt < 2; mt++)
            #pragma unroll
            for (int nt = 0; nt < 8; nt++)
                #pragma unroll
                for (int r = 0; r < 4; r++) acc[mt][nt][r] = 0.f;

        #pragma unroll 4
        for (int kt = 0; kt < 16; kt++) {
            const int kw = kt * 8 + m;
            uint32_t a[2][4];
            #pragma unroll
            for (int mt = 0; mt < 2; mt++) {
                const int base = (warpE + mt * 16 + g) * LDAS;
                a[mt][0] = As32[base + kw];
                a[mt][1] = As32[base + 8 * LDAS + kw];
                a[mt][2] = As32[base + kw + 4];
                a[mt][3] = As32[base + 8 * LDAS + kw + 4];
            }
            #pragma unroll
            for (int nt = 0; nt < 8; nt++) {
                const uint32_t b0  = W1t32[(nt * 8 + g) * LDW + kw];
                const uint32_t b1v = W1t32[(nt * 8 + g) * LDW + kw + 4];
                mma_fp16(acc[0][nt], a[0], b0, b1v);
                mma_fp16(acc[1][nt], a[1], b0, b1v);
            }
        }

        __syncwarp();   // all lanes done reading As rows before overwrite

        // ---- Prefetch next tile's gather; lands during epilogue + other warps ----
        const int nxt = tile + gridDim.x;
        if (nxt < nTiles) issue_gather(ctx, nxt);

        // ---- Epilogue: bias + ReLU + W2 dot + sigmoid ----
        float p[4] = {0.f, 0.f, 0.f, 0.f};  // rows g, g+8, g+16, g+24
        #pragma unroll
        for (int mt = 0; mt < 2; mt++) {
            #pragma unroll
            for (int nt = 0; nt < 8; nt++) {
                const int c = nt * 8 + 2 * m;
                const float ba = b1s[c], bb = b1s[c + 1];
                const float wa = w2s[c], wb = w2s[c + 1];
                float h;
                h = acc[mt][nt][0] + ba; p[mt * 2 + 0] += fmaxf(h, 0.f) * wa;
                h = acc[mt][nt][1] + bb; p[mt * 2 + 0] += fmaxf(h, 0.f) * wb;
                h = acc[mt][nt][2] + ba; p[mt * 2 + 1] += fmaxf(h, 0.f) * wa;
                h = acc[mt][nt][3] + bb; p[mt * 2 + 1] += fmaxf(h, 0.f) * wb;
            }
        }
        #pragma unroll
        for (int j = 0; j < 4; j++) {
            p[j] += __shfl_xor_sync(0xffffffffu, p[j], 1);
            p[j] += __shfl_xor_sync(0xffffffffu, p[j], 2);
        }
        if (m == 0) {
            const float bias2 = b2s[0];
            const int tileBase = tile * TILE_E;
            #pragma unroll
            for (int j = 0; j < 4; j++) {
                const int e = tileBase + warpE + (j >> 1) * 16 + (j & 1) * 8 + g;
                if (e < NE)
                    out[e] = 1.f / (1.f + __expf(-(p[j] + bias2)));
            }
        }
    }
}

extern "C" void kernel_launch(void* const* d_in, const int* in_sizes, int n_in,
                              void* d_out, int out_size) {
    const float* z    = (const float*)d_in[0];
    const void*  eidx = d_in[1];
    const float* W1   = (const float*)d_in[2];
    const float* b1   = (const float*)d_in[3];
    const float* W2   = (const float*)d_in[4];
    const float* b2   = (const float*)d_in[5];
    float*       out  = (float*)d_out;

    const int NE = in_sizes[1] / 2;  // edge_index is (2, E)
    const int nZ = in_sizes[0];      // N_NODES * IN_DIM

    static bool attr_set = false;
    if (!attr_set) {
        cudaFuncSetAttribute(mask_predictor_kernel,
                             cudaFuncAttributeMaxDynamicSharedMemorySize, SMEM_BYTES);
        attr_set = true;
    }

    convert_z_kernel<<<152, 256>>>(z, nZ);
    mask_predictor_kernel<<<GRID, NTHREADS, SMEM_BYTES>>>(eidx, W1, b1, W2, b2, out, NE);
}

// round 8
// speedup vs baseline: 4.1089x; 1.0273x over previous
#include <cuda_runtime.h>
#include <cuda_fp16.h>
#include <cstdint>

// Shapes fixed by the reference
#define N_NODES  100000
#define IN_DIM   128
#define KDIM     256          // 2*IN_DIM
#define HID      64
#define WARPS    11           // warps per block (one block per SM)
#define NTHREADS (WARPS*32)
#define CHUNK_E  32           // edges per warp chunk
#define LDAS     132          // As row stride in 32-bit words (128 data + 4 pad)
#define LDW      132          // W1t row stride in 32-bit words (128 data + 4 pad)
#define GRID     152          // 1 block per SM

#define SMEM_BYTES (WARPS*CHUNK_E*LDAS*4 + HID*LDW*4 + (64+64+1)*4)

// fp16 copy of z, gathered via cp.async (25.6 MB static scratch)
__device__ __half zh_g[N_NODES * IN_DIM];

__global__ void convert_z_kernel(const float* __restrict__ z, int n) {
    const int stride = gridDim.x * blockDim.x;
    const int n4 = n >> 2;
    const float4* z4 = reinterpret_cast<const float4*>(z);
    __half2* o2 = reinterpret_cast<__half2*>(zh_g);
    for (int i = blockIdx.x * blockDim.x + threadIdx.x; i < n4; i += stride) {
        float4 v = z4[i];
        o2[i * 2 + 0] = __floats2half2_rn(v.x, v.y);
        o2[i * 2 + 1] = __floats2half2_rn(v.z, v.w);
    }
}

__device__ __forceinline__ void mma_fp16(float* c, const uint32_t* a,
                                         uint32_t b0, uint32_t b1) {
    asm volatile(
        "mma.sync.aligned.m16n8k16.row.col.f32.f16.f16.f32 "
        "{%0,%1,%2,%3}, {%4,%5,%6,%7}, {%8,%9}, {%0,%1,%2,%3};"
        : "+f"(c[0]), "+f"(c[1]), "+f"(c[2]), "+f"(c[3])
        : "r"(a[0]), "r"(a[1]), "r"(a[2]), "r"(a[3]), "r"(b0), "r"(b1));
}

struct GatherCtx {
    const int* e32;
    const long long* e64;
    bool is64;
    const char* zb;
    uint32_t* As32;           // this warp's 32-row slab
    int NE, lane, halfSel, sub;
};

// Issue cp.async gather of one 32-edge chunk into this warp's slab (no waits).
__device__ __forceinline__ void issue_gather(const GatherCtx& c, int chunk) {
    const int ge = chunk * CHUNK_E + c.lane;
    long long sIdx = 0, dIdx = 0;
    if (ge < c.NE) {
        if (c.is64) { sIdx = c.e64[ge]; dIdx = c.e64[(long long)c.NE + ge]; }
        else        { sIdx = (long long)c.e32[ge]; dIdx = (long long)c.e32[c.NE + ge]; }
    }
    #pragma unroll 8
    for (int i = 0; i < 32; i++) {
        const long long s = __shfl_sync(0xffffffffu, sIdx, i);
        const long long d = __shfl_sync(0xffffffffu, dIdx, i);
        const long long row = c.halfSel ? d : s;
        const char* src = c.zb + (row << 8) + c.sub * 16;
        char* dstp = reinterpret_cast<char*>(c.As32)
                   + i * (LDAS * 4) + c.halfSel * 256 + c.sub * 16;
        const uint32_t daddr = (uint32_t)__cvta_generic_to_shared(dstp);
        asm volatile("cp.async.cg.shared.global [%0], [%1], 16;\n"
                     :: "r"(daddr), "l"(src));
    }
    asm volatile("cp.async.commit_group;\n");
}

__global__ __launch_bounds__(NTHREADS, 1)
void mask_predictor_kernel(const void* __restrict__ eidx_raw,
                           const float* __restrict__ W1,
                           const float* __restrict__ b1,
                           const float* __restrict__ W2,
                           const float* __restrict__ b2,
                           float* __restrict__ out,
                           int NE) {
    extern __shared__ unsigned char smem_raw[];
    uint32_t* As32  = reinterpret_cast<uint32_t*>(smem_raw);     // [352][132] words (fp16x2)
    uint32_t* W1t32 = As32 + WARPS * CHUNK_E * LDAS;             // [64][132] words (W1^T)
    float*    b1s   = reinterpret_cast<float*>(W1t32 + HID * LDW);
    float*    w2s   = b1s + 64;
    float*    b2s   = w2s + 64;
    __half*   W1th  = reinterpret_cast<__half*>(W1t32);          // halves, row stride 264

    const int tid  = threadIdx.x;
    const int warp = tid >> 5;
    const int lane = tid & 31;
    const int g    = lane >> 2;   // groupID (0..7)
    const int m    = lane & 3;    // thread-in-group (0..3)

    // ---- Detect edge_index dtype (int64 vs int32) uniformly ----
    const int*       e32 = reinterpret_cast<const int*>(eidx_raw);
    const long long* e64 = reinterpret_cast<const long long*>(eidx_raw);
    bool is64 = true;
    #pragma unroll
    for (int i = 1; i < 32; i += 2) if (e32[i] != 0) is64 = false;

    // ---- Stage W1^T (fp16), b1, W2, b2 (read-only after this barrier) ----
    for (int i = tid; i < KDIM * HID; i += NTHREADS) {
        const int k = i >> 6, n = i & 63;
        W1th[n * (LDW * 2) + k] = __float2half(W1[i]);
    }
    if (tid < 64) { b1s[tid] = b1[tid]; w2s[tid] = W2[tid]; }
    if (tid == 64) { b2s[0] = b2[0]; }
    __syncthreads();

    uint32_t* myAs = As32 + warp * CHUNK_E * LDAS;  // this warp's private slab

    GatherCtx ctx;
    ctx.e32 = e32; ctx.e64 = e64; ctx.is64 = is64;
    ctx.zb = reinterpret_cast<const char*>(zh_g);
    ctx.As32 = myAs; ctx.NE = NE;
    ctx.lane = lane;
    ctx.halfSel = lane >> 4;
    ctx.sub = lane & 15;

    // Each warp is an independent pipeline over its own 32-row slab; work is
    // global-warp-strided 32-edge chunks. No block barriers in the loop.
    const int nChunks = (NE + CHUNK_E - 1) / CHUNK_E;
    const int wStride = GRID * WARPS;

    int chunk = blockIdx.x * WARPS + warp;
    if (chunk < nChunks) issue_gather(ctx, chunk);

    for (; chunk < nChunks; chunk += wStride) {
        asm volatile("cp.async.wait_group 0;\n" ::: "memory");
        __syncwarp();   // make lane-written As rows visible warp-wide

        // ---- GEMM: warp computes 32 edges x 64 cols, fp16 m16n8k16, fp32 acc ----
        float acc[2][8][4];
        #pragma unroll
        for (int mt = 0; mt < 2; mt++)
            #pragma unroll
            for (int nt = 0; nt < 8; nt++)
                #pragma unroll
                for (int r = 0; r < 4; r++) acc[mt][nt][r] = 0.f;

        #pragma unroll 4
        for (int kt = 0; kt < 16; kt++) {
            const int kw = kt * 8 + m;
            uint32_t a[2][4];
            #pragma unroll
            for (int mt = 0; mt < 2; mt++) {
                const int base = (mt * 16 + g) * LDAS;
                a[mt][0] = myAs[base + kw];
                a[mt][1] = myAs[base + 8 * LDAS + kw];
                a[mt][2] = myAs[base + kw + 4];
                a[mt][3] = myAs[base + 8 * LDAS + kw + 4];
            }
            #pragma unroll
            for (int nt = 0; nt < 8; nt++) {
                const uint32_t b0  = W1t32[(nt * 8 + g) * LDW + kw];
                const uint32_t b1v = W1t32[(nt * 8 + g) * LDW + kw + 4];
                mma_fp16(acc[0][nt], a[0], b0, b1v);
                mma_fp16(acc[1][nt], a[1], b0, b1v);
            }
        }

        __syncwarp();   // all lanes done reading As before overwrite

        // ---- Prefetch next chunk's gather; lands during epilogue + peers ----
        const int nxt = chunk + wStride;
        if (nxt < nChunks) issue_gather(ctx, nxt);

        // ---- Epilogue: bias + ReLU + W2 dot + sigmoid ----
        float p[4] = {0.f, 0.f, 0.f, 0.f};  // rows g, g+8, g+16, g+24
        #pragma unroll
        for (int mt = 0; mt < 2; mt++) {
            #pragma unroll
            for (int nt = 0; nt < 8; nt++) {
                const int c = nt * 8 + 2 * m;
                const float ba = b1s[c], bb = b1s[c + 1];
                const float wa = w2s[c], wb = w2s[c + 1];
                float h;
                h = acc[mt][nt][0] + ba; p[mt * 2 + 0] += fmaxf(h, 0.f) * wa;
                h = acc[mt][nt][1] + bb; p[mt * 2 + 0] += fmaxf(h, 0.f) * wb;
                h = acc[mt][nt][2] + ba; p[mt * 2 + 1] += fmaxf(h, 0.f) * wa;
                h = acc[mt][nt][3] + bb; p[mt * 2 + 1] += fmaxf(h, 0.f) * wb;
            }
        }
        #pragma unroll
        for (int j = 0; j < 4; j++) {
            p[j] += __shfl_xor_sync(0xffffffffu, p[j], 1);
            p[j] += __shfl_xor_sync(0xffffffffu, p[j], 2);
        }
        if (m == 0) {
            const float bias2 = b2s[0];
            const int base = chunk * CHUNK_E;
            #pragma unroll
            for (int j = 0; j < 4; j++) {
                const int e = base + (j >> 1) * 16 + (j & 1) * 8 + g;
                if (e < NE)
                    out[e] = 1.f / (1.f + __expf(-(p[j] + bias2)));
            }
        }
    }
}

extern "C" void kernel_launch(void* const* d_in, const int* in_sizes, int n_in,
                              void* d_out, int out_size) {
    const float* z    = (const float*)d_in[0];
    const void*  eidx = d_in[1];
    const float* W1   = (const float*)d_in[2];
    const float* b1   = (const float*)d_in[3];
    const float* W2   = (const float*)d_in[4];
    const float* b2   = (const float*)d_in[5];
    float*       out  = (float*)d_out;

    const int NE = in_sizes[1] / 2;  // edge_index is (2, E)
    const int nZ = in_sizes[0];      // N_NODES * IN_DIM

    static bool attr_set = false;
    if (!attr_set) {
        cudaFuncSetAttribute(mask_predictor_kernel,
                             cudaFuncAttributeMaxDynamicSharedMemorySize, SMEM_BYTES);
        attr_set = true;
    }

    convert_z_kernel<<<152, 256>>>(z, nZ);
    mask_predictor_kernel<<<GRID, NTHREADS, SMEM_BYTES>>>(eidx, W1, b1, W2, b2, out, NE);
}